// round 5
// baseline (speedup 1.0000x reference)
#include <cuda_runtime.h>
#include <cuda_bf16.h>
#include <cstdint>

#define BIGV 10000000000.0f
#define F_L2E 1.4426950408889634f
#define F_LN2 0.6931471805599453f

// D (pre-scaled by log2(e)) in anti-diagonal-major layout:
// g_D[b][kd][i0] = log2e * D[b][i0][j0], kd = i0 + j0 (0-based), dims [64][1024][512].
__device__ float g_D[(size_t)64 * 1024 * 512];

__device__ __forceinline__ float ex2f_(float x) {
    float r; asm("ex2.approx.f32 %0, %1;" : "=f"(r) : "f"(x)); return r;
}
__device__ __forceinline__ float lg2f_(float x) {
    float r; asm("lg2.approx.f32 %0, %1;" : "=f"(r) : "f"(x)); return r;
}
__device__ __forceinline__ void st_release_shared(int* p, int v) {
    unsigned a = (unsigned)__cvta_generic_to_shared(p);
    asm volatile("st.release.cta.shared.b32 [%0], %1;" :: "r"(a), "r"(v) : "memory");
}
__device__ __forceinline__ int ld_acquire_shared(const int* p) {
    unsigned a = (unsigned)__cvta_generic_to_shared(p);
    int v; asm volatile("ld.acquire.cta.shared.b32 %0, [%1];" : "=r"(v) : "r"(a) : "memory");
    return v;
}

// ---------------------------------------------------------------------------
// Kernel 1: squared distances * log2e, written anti-diagonal-major.
// ---------------------------------------------------------------------------
__global__ __launch_bounds__(256) void sqdist_kernel(const float* __restrict__ x,
                                                     const float* __restrict__ y)
{
    __shared__ __align__(16) float xs[16][64];
    __shared__ __align__(16) float ys[16][64];
    __shared__ float x2s[64], y2s[64];
    __shared__ float ts[64][66];

    const int b   = blockIdx.z;
    const int i0  = blockIdx.y * 64;
    const int j0  = blockIdx.x * 64;
    const int tid = threadIdx.x;

    {
        int row = tid >> 2;
        int d0  = (tid & 3) * 4;
        float4 xv = *(const float4*)(x + ((size_t)(b * 512 + i0 + row)) * 16 + d0);
        xs[d0 + 0][row] = xv.x; xs[d0 + 1][row] = xv.y;
        xs[d0 + 2][row] = xv.z; xs[d0 + 3][row] = xv.w;
        float4 yv = *(const float4*)(y + ((size_t)(b * 512 + j0 + row)) * 16 + d0);
        ys[d0 + 0][row] = yv.x; ys[d0 + 1][row] = yv.y;
        ys[d0 + 2][row] = yv.z; ys[d0 + 3][row] = yv.w;
    }
    __syncthreads();

    if (tid < 64) {
        float s = 0.f;
        #pragma unroll
        for (int d = 0; d < 16; d++) s += xs[d][tid] * xs[d][tid];
        x2s[tid] = s;
    } else if (tid < 128) {
        int c = tid - 64;
        float s = 0.f;
        #pragma unroll
        for (int d = 0; d < 16; d++) s += ys[d][c] * ys[d][c];
        y2s[c] = s;
    }
    __syncthreads();

    const int tx = tid & 15;
    const int ty = tid >> 4;
    float acc[4][4];
    #pragma unroll
    for (int r = 0; r < 4; r++)
        #pragma unroll
        for (int c = 0; c < 4; c++) acc[r][c] = 0.f;

    #pragma unroll
    for (int d = 0; d < 16; d++) {
        float4 av = *(const float4*)&xs[d][ty * 4];
        float4 bv = *(const float4*)&ys[d][tx * 4];
        float a[4]  = {av.x, av.y, av.z, av.w};
        float bb[4] = {bv.x, bv.y, bv.z, bv.w};
        #pragma unroll
        for (int r = 0; r < 4; r++)
            #pragma unroll
            for (int c = 0; c < 4; c++) acc[r][c] = fmaf(a[r], bb[c], acc[r][c]);
    }

    #pragma unroll
    for (int r = 0; r < 4; r++) {
        float xv2 = x2s[ty * 4 + r];
        #pragma unroll
        for (int c = 0; c < 4; c++)
            ts[ty * 4 + r][tx * 4 + c] = fmaf(-2.f, acc[r][c], xv2 + y2s[tx * 4 + c]);
    }
    __syncthreads();

    const size_t bbase = ((size_t)b) << 19;
    for (int idx = tid; idx < 127 * 64; idx += 256) {
        int kk = idx >> 6;
        int ii = idx & 63;
        int jj = kk - ii;
        if ((unsigned)jj < 64u)
            g_D[bbase + ((size_t)(i0 + j0 + kk) << 9) + (size_t)(i0 + ii)]
                = ts[ii][jj] * F_L2E;
    }
}

// ---------------------------------------------------------------------------
// Kernel 2: soft-DTW wavefront, 2 rows/thread, lane-skew 2.
// One block per batch, 256 threads = 8 warps; thread t owns rows i1=2t+1,
// i2=2t+2 (1-based). At warp-local step q, lane l computes columns
// j1 = q+1-2l (row1) and j2 = q-2l (row2). Row2 needs only the thread's own
// row1 registers (up2 = r1P1, dg2 = r1P2); row1 needs one shfl (up1 = lane
// l-1's r2P1) and reuses last step's shfl as dg1. Both rows share anti-diag
// index kd = 64w+q -> one float2 load per step.
// Cross-warp boundary: lane31 row2 values in ring[w+1][col], col = q-62;
// progress per 8-step chunk via st.release / ld.acquire (+8 slack, cached).
// Values carry an implicit log2(e) factor; softmin = 2x ex2 + 1x lg2 per row.
// ---------------------------------------------------------------------------
__global__ __launch_bounds__(256) void dtw_kernel(float* __restrict__ out)
{
    __shared__ float ring[9][516];
    __shared__ int prog[9];

    const int b    = blockIdx.x;
    const int tid  = threadIdx.x;
    const int lane = tid & 31;
    const int w    = tid >> 5;
    const bool lane0 = (lane == 0);

    // ring[0] = virtual boundary row 0 for warp 0: all BIG.
    for (int idx = tid; idx < 516; idx += 256) ring[0][idx] = BIGV;
    if (tid < 9) prog[tid] = 0;
    __syncthreads();

    const float2* __restrict__ Dp2 = (const float2*)g_D + (((size_t)b) << 18) + (size_t)tid;
    const float* __restrict__ ringR = ring[w];
    float*       __restrict__ ringW = ring[w + 1];
    const int kbase = w << 6;             // 64*w

    float r1P1 = BIGV, r1P2 = BIGV, r2P1 = BIGV;
    float shvPrev = BIGV;
    float ringPrev, ringUp;

    float2 cur[8], nxt[8];
    #pragma unroll
    for (int s = 0; s < 8; ++s) cur[s] = Dp2[(size_t)(kbase + s) << 8];

    int pcache = 0;
    // First wait (covers ring cols through 17) + boundary preload.
    if (w) {
        int p = ld_acquire_shared(&prog[w]);
        while (p < 17) { __nanosleep(32); p = ld_acquire_shared(&prog[w]); }
        pcache = p;
    }
    ringUp   = ringR[1];                       // col 1 (up1 at q=0)
    ringPrev = (w == 0) ? 0.0f : BIGV;          // col 0: R[0][0]=0 else BIG

#define DTW_WAIT(C) do {                                                        \
        if (w) {                                                                \
            int need_ = 8 * (C) + 17; if (need_ > 512) need_ = 512;             \
            if (pcache < need_) {                                               \
                int p_ = ld_acquire_shared(&prog[w]);                           \
                while (p_ < need_) { __nanosleep(32);                           \
                                     p_ = ld_acquire_shared(&prog[w]); }        \
                pcache = p_;                                                    \
            }                                                                   \
        }                                                                       \
    } while (0)

#define DTW_PUB(C) do {                                                         \
        int pub_ = 8 * (C) - 55; if (pub_ > 512) pub_ = 512;                    \
        if (lane == 31 && pub_ > 0) st_release_shared(&prog[w + 1], pub_);      \
    } while (0)

// PHASE: 0 = ramp-in, 1 = steady, 2 = ramp-out
#define DTW_STEP(S, QV, PHASE) do {                                             \
        float2 dpair_ = cur[S];                                                 \
        float shv_ = __shfl_up_sync(0xffffffffu, r2P1, 1);                      \
        float up1_ = lane0 ? ringUp : shv_;                                     \
        float dg1_ = lane0 ? ringPrev : shvPrev;                                \
        ringPrev = ringUp;                                                      \
        { int rc_ = (QV) + 2; if (rc_ > 515) rc_ = 515; ringUp = ringR[rc_]; }  \
        shvPrev = shv_;                                                         \
        /* row1: a=dg1, b=up1(late), c=left=r1P1 */                             \
        float lo1_ = fminf(dg1_, r1P1), hi1_ = fmaxf(dg1_, r1P1);               \
        float mn1_ = fminf(lo1_, up1_);                                         \
        float mid1_ = fminf(fmaxf(lo1_, up1_), hi1_);                           \
        float mx1_ = fmaxf(hi1_, up1_);                                         \
        float t1_ = ex2f_(mn1_ - mid1_) + ex2f_(mn1_ - mx1_);                   \
        float rn1_ = dpair_.x + mn1_ - lg2f_(1.0f + t1_);                       \
        /* row2: a=dg=r1P2, b=up=r1P1, c=left=r2P1 (all step-start regs) */     \
        float lo2_ = fminf(r1P2, r2P1), hi2_ = fmaxf(r1P2, r2P1);               \
        float mn2_ = fminf(lo2_, r1P1);                                         \
        float mid2_ = fminf(fmaxf(lo2_, r1P1), hi2_);                           \
        float mx2_ = fmaxf(hi2_, r1P1);                                         \
        float t2_ = ex2f_(mn2_ - mid2_) + ex2f_(mn2_ - mx2_);                   \
        float rn2_ = dpair_.y + mn2_ - lg2f_(1.0f + t2_);                       \
        if (PHASE == 0) {                                                       \
            rn1_ = (2 * lane <= (QV)) ? rn1_ : BIGV;                            \
            rn2_ = (2 * lane <  (QV)) ? rn2_ : BIGV;                            \
        } else if (PHASE == 2) {                                                \
            rn1_ = ((QV) <= 2 * lane + 511) ? rn1_ : BIGV;                      \
            rn2_ = ((QV) <= 2 * lane + 512) ? rn2_ : BIGV;                      \
        }                                                                       \
        r1P2 = r1P1; r1P1 = rn1_; r2P1 = rn2_;                                  \
        if (PHASE == 0) {                                                       \
            if (lane == 31 && (QV) >= 63) ringW[(QV) - 62] = rn2_;              \
        } else if (PHASE == 1) {                                                \
            if (lane == 31) ringW[(QV) - 62] = rn2_;                            \
        } else {                                                                \
            if (lane == 31 && (QV) <= 574) ringW[(QV) - 62] = rn2_;             \
            if ((QV) == 574 && tid == 255) out[b] = rn2_ * F_LN2;               \
        }                                                                       \
    } while (0)

    // ---- ramp-in: chunks 0..7 (q = 0..63) ----
    #pragma unroll 1
    for (int c = 0; c < 8; ++c) {
        DTW_WAIT(c);
        int kn = kbase + 8 * (c + 1);
        #pragma unroll
        for (int s = 0; s < 8; ++s) nxt[s] = Dp2[(size_t)(kn + s) << 8];
        #pragma unroll
        for (int s = 0; s < 8; ++s) DTW_STEP(s, 8 * c + s, 0);
        #pragma unroll
        for (int s = 0; s < 8; ++s) cur[s] = nxt[s];
        DTW_PUB(c);
    }

    // ---- steady: chunks 8..63 (q = 64..511), all cells valid ----
    #pragma unroll 1
    for (int c = 8; c < 64; ++c) {
        DTW_WAIT(c);
        int kn = kbase + 8 * (c + 1);
        #pragma unroll
        for (int s = 0; s < 8; ++s) nxt[s] = Dp2[(size_t)(kn + s) << 8];
        #pragma unroll
        for (int s = 0; s < 8; ++s) DTW_STEP(s, 8 * c + s, 1);
        #pragma unroll
        for (int s = 0; s < 8; ++s) cur[s] = nxt[s];
        DTW_PUB(c);
    }

    // ---- ramp-out: chunks 64..71 (q = 512..575) ----
    #pragma unroll 1
    for (int c = 64; c < 72; ++c) {
        DTW_WAIT(c);
        int kn = kbase + 8 * (c + 1);
        #pragma unroll
        for (int s = 0; s < 8; ++s) {
            int kd = kn + s; if (kd > 1023) kd = 1023;
            nxt[s] = Dp2[(size_t)kd << 8];
        }
        #pragma unroll
        for (int s = 0; s < 8; ++s) DTW_STEP(s, 8 * c + s, 2);
        #pragma unroll
        for (int s = 0; s < 8; ++s) cur[s] = nxt[s];
        DTW_PUB(c);
    }

#undef DTW_STEP
#undef DTW_PUB
#undef DTW_WAIT
}

extern "C" void kernel_launch(void* const* d_in, const int* in_sizes, int n_in,
                              void* d_out, int out_size)
{
    const float* x = (const float*)d_in[0];
    const float* y = (const float*)d_in[1];
    float* out = (float*)d_out;

    dim3 g1(8, 8, 64);
    sqdist_kernel<<<g1, 256>>>(x, y);
    dtw_kernel<<<64, 256>>>(out);
}

// round 6
// speedup vs baseline: 1.0285x; 1.0285x over previous
#include <cuda_runtime.h>
#include <cuda_bf16.h>
#include <cstdint>

#define BIGV 10000000000.0f
#define F_L2E 1.4426950408889634f
#define F_LN2 0.6931471805599453f

// D (pre-scaled by log2(e)) in anti-diagonal-major layout:
// g_D[b][kd][i0] = log2e * D[b][i0][j0], kd = i0 + j0 (0-based), dims [64][1024][512].
__device__ float g_D[(size_t)64 * 1024 * 512];
// Cross-block boundary ring: g_ring[b][j] = R[256][j] (scaled), j in 1..512.
__device__ float g_ring[64][520];
__device__ int   g_prog[64];

__device__ __forceinline__ float ex2f_(float x) {
    float r; asm("ex2.approx.f32 %0, %1;" : "=f"(r) : "f"(x)); return r;
}
__device__ __forceinline__ float lg2f_(float x) {
    float r; asm("lg2.approx.f32 %0, %1;" : "=f"(r) : "f"(x)); return r;
}
__device__ __forceinline__ void st_release_shared(int* p, int v) {
    unsigned a = (unsigned)__cvta_generic_to_shared(p);
    asm volatile("st.release.cta.shared.b32 [%0], %1;" :: "r"(a), "r"(v) : "memory");
}
__device__ __forceinline__ int ld_acquire_shared(const int* p) {
    unsigned a = (unsigned)__cvta_generic_to_shared(p);
    int v; asm volatile("ld.acquire.cta.shared.b32 %0, [%1];" : "=r"(v) : "r"(a) : "memory");
    return v;
}
__device__ __forceinline__ void st_release_gpu(int* p, int v) {
    asm volatile("st.release.gpu.global.b32 [%0], %1;" :: "l"(p), "r"(v) : "memory");
}
__device__ __forceinline__ int ld_acquire_gpu(const int* p) {
    int v; asm volatile("ld.acquire.gpu.global.b32 %0, [%1];" : "=r"(v) : "l"(p) : "memory");
    return v;
}
__device__ __forceinline__ float ldg_cg(const float* p) {
    float v; asm volatile("ld.global.cg.f32 %0, [%1];" : "=f"(v) : "l"(p) : "memory");
    return v;
}

__global__ void init_prog_kernel() {
    if (threadIdx.x < 64) g_prog[threadIdx.x] = 0;
}

// ---------------------------------------------------------------------------
// Kernel 1: squared distances * log2e, written anti-diagonal-major.
// ---------------------------------------------------------------------------
__global__ __launch_bounds__(256) void sqdist_kernel(const float* __restrict__ x,
                                                     const float* __restrict__ y)
{
    __shared__ __align__(16) float xs[16][64];
    __shared__ __align__(16) float ys[16][64];
    __shared__ float x2s[64], y2s[64];
    __shared__ float ts[64][66];

    const int b   = blockIdx.z;
    const int i0  = blockIdx.y * 64;
    const int j0  = blockIdx.x * 64;
    const int tid = threadIdx.x;

    {
        int row = tid >> 2;
        int d0  = (tid & 3) * 4;
        float4 xv = *(const float4*)(x + ((size_t)(b * 512 + i0 + row)) * 16 + d0);
        xs[d0 + 0][row] = xv.x; xs[d0 + 1][row] = xv.y;
        xs[d0 + 2][row] = xv.z; xs[d0 + 3][row] = xv.w;
        float4 yv = *(const float4*)(y + ((size_t)(b * 512 + j0 + row)) * 16 + d0);
        ys[d0 + 0][row] = yv.x; ys[d0 + 1][row] = yv.y;
        ys[d0 + 2][row] = yv.z; ys[d0 + 3][row] = yv.w;
    }
    __syncthreads();

    if (tid < 64) {
        float s = 0.f;
        #pragma unroll
        for (int d = 0; d < 16; d++) s += xs[d][tid] * xs[d][tid];
        x2s[tid] = s;
    } else if (tid < 128) {
        int c = tid - 64;
        float s = 0.f;
        #pragma unroll
        for (int d = 0; d < 16; d++) s += ys[d][c] * ys[d][c];
        y2s[c] = s;
    }
    __syncthreads();

    const int tx = tid & 15;
    const int ty = tid >> 4;
    float acc[4][4];
    #pragma unroll
    for (int r = 0; r < 4; r++)
        #pragma unroll
        for (int c = 0; c < 4; c++) acc[r][c] = 0.f;

    #pragma unroll
    for (int d = 0; d < 16; d++) {
        float4 av = *(const float4*)&xs[d][ty * 4];
        float4 bv = *(const float4*)&ys[d][tx * 4];
        float a[4]  = {av.x, av.y, av.z, av.w};
        float bb[4] = {bv.x, bv.y, bv.z, bv.w};
        #pragma unroll
        for (int r = 0; r < 4; r++)
            #pragma unroll
            for (int c = 0; c < 4; c++) acc[r][c] = fmaf(a[r], bb[c], acc[r][c]);
    }

    #pragma unroll
    for (int r = 0; r < 4; r++) {
        float xv2 = x2s[ty * 4 + r];
        #pragma unroll
        for (int c = 0; c < 4; c++)
            ts[ty * 4 + r][tx * 4 + c] = fmaf(-2.f, acc[r][c], xv2 + y2s[tx * 4 + c]);
    }
    __syncthreads();

    const size_t bbase = ((size_t)b) << 19;
    for (int idx = tid; idx < 127 * 64; idx += 256) {
        int kk = idx >> 6;
        int ii = idx & 63;
        int jj = kk - ii;
        if ((unsigned)jj < 64u)
            g_D[bbase + ((size_t)(i0 + j0 + kk) << 9) + (size_t)(i0 + ii)]
                = ts[ii][jj] * F_L2E;
    }
}

// ---------------------------------------------------------------------------
// Kernel 2: soft-DTW wavefront, 2 rows/thread, 2 blocks per batch.
// Block bx: batch b = bx>>1, half h = bx&1 (rows 256h+1 .. 256h+256).
// 128 threads = 4 warps; thread t owns rows i1 = 256h+2t+1, i2 = i1+1.
// Global warp index W = 4h + (t>>5); at warp step q, lane l computes columns
// j1 = q+1-2l (row1), j2 = q-2l (row2); anti-diag kd = 64W + q.
// Intra-block handoff: smem ring + prog (release/acquire). Cross-block hop:
// block 0 warp 3 writes g_ring[b] + g_prog[b] (release.gpu); block 1 warp 0
// stages g_ring chunks into its smem ring[0] (ld.global.cg + syncwarp).
// ---------------------------------------------------------------------------
__global__ __launch_bounds__(128) void dtw_kernel(float* __restrict__ out)
{
    __shared__ float ring[5][520];
    __shared__ int prog[5];

    const int bx   = blockIdx.x;
    const int b    = bx >> 1;
    const int h    = bx & 1;
    const int tid  = threadIdx.x;
    const int lane = tid & 31;
    const int wl   = tid >> 5;            // 0..3
    const int W    = 4 * h + wl;          // 0..7 global warp
    const bool lane0 = (lane == 0);
    const bool is_gprod = (h == 0) && (wl == 3);
    const bool is_gcons = (h == 1) && (wl == 0);

    for (int idx = tid; idx < 520; idx += 128) ring[0][idx] = BIGV;
    if (tid < 5) prog[tid] = 0;
    __syncthreads();

    // float2 row-pair pointer: row pair index = 128h + t.
    const float2* __restrict__ Dp2 =
        (const float2*)g_D + (((size_t)b) << 18) + (size_t)(128 * h + tid);
    const float* __restrict__ ringR = ring[wl];
    float* ringW = is_gprod ? g_ring[b] : ring[wl + 1];
    const int kbase = W << 6;             // 64*W

    float r1P1 = BIGV, r1P2 = BIGV, r2P1 = BIGV;
    float shvPrev = BIGV;
    float ringPrev, ringUp;

    float2 cur[8], nxt[8];
    #pragma unroll
    for (int s = 0; s < 8; ++s) cur[s] = Dp2[(size_t)(kbase + s) << 8];

    int pcache = 0;
    // Initial wait + boundary preload.
    if (is_gcons) {
        int p = ld_acquire_gpu(&g_prog[b]);
        while (p < 17) { __nanosleep(64); p = ld_acquire_gpu(&g_prog[b]); }
        pcache = p;
        if (lane < 9) ring[0][1 + lane] = ldg_cg(&g_ring[b][1 + lane]);
        __syncwarp();
    } else if (wl != 0) {
        int p = ld_acquire_shared(&prog[wl]);
        while (p < 17) { __nanosleep(32); p = ld_acquire_shared(&prog[wl]); }
        pcache = p;
    }
    ringUp   = ringR[1];                        // col 1 (up1 at q=0)
    ringPrev = (W == 0) ? 0.0f : BIGV;          // col 0: R[0][0]=0 else BIG

#define DTW_WAIT(C) do {                                                        \
        if (is_gcons) {                                                         \
            int need_ = 8 * (C) + 17; if (need_ > 512) need_ = 512;             \
            if (pcache < need_) {                                               \
                int p_ = ld_acquire_gpu(&g_prog[b]);                            \
                while (p_ < need_) { __nanosleep(64);                           \
                                     p_ = ld_acquire_gpu(&g_prog[b]); }         \
                pcache = p_;                                                    \
            }                                                                   \
            if ((C) > 0) {                                                      \
                int pos_ = 8 * (C) + 2 + lane; if (pos_ > 516) pos_ = 516;      \
                if (lane < 8) ring[0][pos_] = ldg_cg(&g_ring[b][pos_]);         \
            }                                                                   \
            __syncwarp();                                                       \
        } else if (wl != 0) {                                                   \
            int need_ = 8 * (C) + 17; if (need_ > 512) need_ = 512;             \
            if (pcache < need_) {                                               \
                int p_ = ld_acquire_shared(&prog[wl]);                          \
                while (p_ < need_) { __nanosleep(32);                           \
                                     p_ = ld_acquire_shared(&prog[wl]); }       \
                pcache = p_;                                                    \
            }                                                                   \
        }                                                                       \
    } while (0)

#define DTW_PUB(C) do {                                                         \
        int pub_ = 8 * (C) - 55; if (pub_ > 512) pub_ = 512;                    \
        if (lane == 31 && pub_ > 0) {                                           \
            if (is_gprod) st_release_gpu(&g_prog[b], pub_);                     \
            else          st_release_shared(&prog[wl + 1], pub_);               \
        }                                                                       \
    } while (0)

// PHASE: 0 = ramp-in, 1 = steady, 2 = ramp-out
#define DTW_STEP(S, QV, PHASE) do {                                             \
        float2 dpair_ = cur[S];                                                 \
        float shv_ = __shfl_up_sync(0xffffffffu, r2P1, 1);                      \
        float up1_ = lane0 ? ringUp : shv_;                                     \
        float dg1_ = lane0 ? ringPrev : shvPrev;                                \
        ringPrev = ringUp;                                                      \
        if (PHASE == 2) { int rc_ = (QV) + 2; if (rc_ > 519) rc_ = 519;         \
                          ringUp = ringR[rc_]; }                                \
        else            { ringUp = ringR[(QV) + 2]; }                           \
        shvPrev = shv_;                                                         \
        float lo1_ = fminf(dg1_, r1P1), hi1_ = fmaxf(dg1_, r1P1);               \
        float mn1_ = fminf(lo1_, up1_);                                         \
        float mid1_ = fminf(fmaxf(lo1_, up1_), hi1_);                           \
        float mx1_ = fmaxf(hi1_, up1_);                                         \
        float t1_ = ex2f_(mn1_ - mid1_) + ex2f_(mn1_ - mx1_);                   \
        float rn1_ = dpair_.x + mn1_ - lg2f_(1.0f + t1_);                       \
        float lo2_ = fminf(r1P2, r2P1), hi2_ = fmaxf(r1P2, r2P1);               \
        float mn2_ = fminf(lo2_, r1P1);                                         \
        float mid2_ = fminf(fmaxf(lo2_, r1P1), hi2_);                           \
        float mx2_ = fmaxf(hi2_, r1P1);                                         \
        float t2_ = ex2f_(mn2_ - mid2_) + ex2f_(mn2_ - mx2_);                   \
        float rn2_ = dpair_.y + mn2_ - lg2f_(1.0f + t2_);                       \
        if (PHASE == 0) {                                                       \
            rn1_ = (2 * lane <= (QV)) ? rn1_ : BIGV;                            \
            rn2_ = (2 * lane <  (QV)) ? rn2_ : BIGV;                            \
        } else if (PHASE == 2) {                                                \
            rn1_ = ((QV) <= 2 * lane + 511) ? rn1_ : BIGV;                      \
            rn2_ = ((QV) <= 2 * lane + 512) ? rn2_ : BIGV;                      \
        }                                                                       \
        r1P2 = r1P1; r1P1 = rn1_; r2P1 = rn2_;                                  \
        if (PHASE == 0) {                                                       \
            if (lane == 31 && (QV) >= 63) ringW[(QV) - 62] = rn2_;              \
        } else if (PHASE == 1) {                                                \
            if (lane == 31) ringW[(QV) - 62] = rn2_;                            \
        } else {                                                                \
            if (lane == 31 && (QV) <= 574) ringW[(QV) - 62] = rn2_;             \
            if ((QV) == 574 && W == 7 && lane == 31) out[b] = rn2_ * F_LN2;     \
        }                                                                       \
    } while (0)

    // ---- ramp-in: chunks 0..7 (q = 0..63) ----
    #pragma unroll 1
    for (int c = 0; c < 8; ++c) {
        DTW_WAIT(c);
        int kn = kbase + 8 * (c + 1);
        #pragma unroll
        for (int s = 0; s < 8; ++s) nxt[s] = Dp2[(size_t)(kn + s) << 8];
        #pragma unroll
        for (int s = 0; s < 8; ++s) DTW_STEP(s, 8 * c + s, 0);
        #pragma unroll
        for (int s = 0; s < 8; ++s) cur[s] = nxt[s];
        DTW_PUB(c);
    }

    // ---- steady: chunks 8..63 (q = 64..511), all cells valid ----
    #pragma unroll 1
    for (int c = 8; c < 64; ++c) {
        DTW_WAIT(c);
        int kn = kbase + 8 * (c + 1);
        #pragma unroll
        for (int s = 0; s < 8; ++s) nxt[s] = Dp2[(size_t)(kn + s) << 8];
        #pragma unroll
        for (int s = 0; s < 8; ++s) DTW_STEP(s, 8 * c + s, 1);
        #pragma unroll
        for (int s = 0; s < 8; ++s) cur[s] = nxt[s];
        DTW_PUB(c);
    }

    // ---- ramp-out: chunks 64..71 (q = 512..575) ----
    #pragma unroll 1
    for (int c = 64; c < 72; ++c) {
        DTW_WAIT(c);
        int kn = kbase + 8 * (c + 1);
        #pragma unroll
        for (int s = 0; s < 8; ++s) {
            int kd = kn + s; if (kd > 1023) kd = 1023;
            nxt[s] = Dp2[(size_t)kd << 8];
        }
        #pragma unroll
        for (int s = 0; s < 8; ++s) DTW_STEP(s, 8 * c + s, 2);
        #pragma unroll
        for (int s = 0; s < 8; ++s) cur[s] = nxt[s];
        DTW_PUB(c);
    }

#undef DTW_STEP
#undef DTW_PUB
#undef DTW_WAIT
}

extern "C" void kernel_launch(void* const* d_in, const int* in_sizes, int n_in,
                              void* d_out, int out_size)
{
    const float* x = (const float*)d_in[0];
    const float* y = (const float*)d_in[1];
    float* out = (float*)d_out;

    init_prog_kernel<<<1, 64>>>();
    dim3 g1(8, 8, 64);
    sqdist_kernel<<<g1, 256>>>(x, y);
    dtw_kernel<<<128, 128>>>(out);
}

// round 7
// speedup vs baseline: 1.0928x; 1.0625x over previous
#include <cuda_runtime.h>
#include <cuda_bf16.h>
#include <cstdint>

#define BIGV 10000000000.0f
#define F_L2E 1.4426950408889634f
#define F_LN2 0.6931471805599453f
#define RW 560   // padded row width of shifted row-major D

// D (pre-scaled by log2(e)), row-major with per-row shift:
// g_D[((b*512)+r)*RW + m + (r&31)] = log2e * D[b][r][m]   (0-based r, m)
// so that thread t (lane l = t&31) reads its 4 cols per iter as an aligned float4
// at offset 4n (n = warp-local iteration).
__device__ float g_D[(size_t)64 * 512 * RW];

__device__ __forceinline__ float ex2f_(float x) {
    float r; asm("ex2.approx.f32 %0, %1;" : "=f"(r) : "f"(x)); return r;
}
__device__ __forceinline__ float lg2f_(float x) {
    float r; asm("lg2.approx.f32 %0, %1;" : "=f"(r) : "f"(x)); return r;
}
__device__ __forceinline__ void st_release_shared(int* p, int v) {
    unsigned a = (unsigned)__cvta_generic_to_shared(p);
    asm volatile("st.release.cta.shared.b32 [%0], %1;" :: "r"(a), "r"(v) : "memory");
}
__device__ __forceinline__ int ld_acquire_shared(const int* p) {
    unsigned a = (unsigned)__cvta_generic_to_shared(p);
    int v; asm volatile("ld.acquire.cta.shared.b32 %0, [%1];" : "=r"(v) : "r"(a) : "memory");
    return v;
}

// softmin of {a,b,c} in log2 domain: mn - lg2(1 + 2^(mn-mid) + 2^(mn-mx))
__device__ __forceinline__ float smin3(float a, float b, float c) {
    float lo = fminf(a, c), hi = fmaxf(a, c);
    float mn  = fminf(lo, b);
    float mid = fminf(fmaxf(lo, b), hi);
    float mx  = fmaxf(hi, b);
    float t = ex2f_(mn - mid) + ex2f_(mn - mx);
    return mn - lg2f_(1.0f + t);
}

// ---------------------------------------------------------------------------
// Kernel 1: squared distances * log2e, written shifted-row-major (coalesced).
// Grid (8, 8, 64): one 64x64 (i,j) tile per block, 256 threads, 4x4 microtile.
// ---------------------------------------------------------------------------
__global__ __launch_bounds__(256) void sqdist_kernel(const float* __restrict__ x,
                                                     const float* __restrict__ y)
{
    __shared__ __align__(16) float xs[16][64];
    __shared__ __align__(16) float ys[16][64];
    __shared__ float x2s[64], y2s[64];
    __shared__ float ts[64][66];

    const int b   = blockIdx.z;
    const int i0  = blockIdx.y * 64;
    const int j0  = blockIdx.x * 64;
    const int tid = threadIdx.x;

    {
        int row = tid >> 2;
        int d0  = (tid & 3) * 4;
        float4 xv = *(const float4*)(x + ((size_t)(b * 512 + i0 + row)) * 16 + d0);
        xs[d0 + 0][row] = xv.x; xs[d0 + 1][row] = xv.y;
        xs[d0 + 2][row] = xv.z; xs[d0 + 3][row] = xv.w;
        float4 yv = *(const float4*)(y + ((size_t)(b * 512 + j0 + row)) * 16 + d0);
        ys[d0 + 0][row] = yv.x; ys[d0 + 1][row] = yv.y;
        ys[d0 + 2][row] = yv.z; ys[d0 + 3][row] = yv.w;
    }
    __syncthreads();

    if (tid < 64) {
        float s = 0.f;
        #pragma unroll
        for (int d = 0; d < 16; d++) s += xs[d][tid] * xs[d][tid];
        x2s[tid] = s;
    } else if (tid < 128) {
        int c = tid - 64;
        float s = 0.f;
        #pragma unroll
        for (int d = 0; d < 16; d++) s += ys[d][c] * ys[d][c];
        y2s[c] = s;
    }
    __syncthreads();

    const int tx = tid & 15;
    const int ty = tid >> 4;
    float acc[4][4];
    #pragma unroll
    for (int r = 0; r < 4; r++)
        #pragma unroll
        for (int c = 0; c < 4; c++) acc[r][c] = 0.f;

    #pragma unroll
    for (int d = 0; d < 16; d++) {
        float4 av = *(const float4*)&xs[d][ty * 4];
        float4 bv = *(const float4*)&ys[d][tx * 4];
        float a[4]  = {av.x, av.y, av.z, av.w};
        float bb[4] = {bv.x, bv.y, bv.z, bv.w};
        #pragma unroll
        for (int r = 0; r < 4; r++)
            #pragma unroll
            for (int c = 0; c < 4; c++) acc[r][c] = fmaf(a[r], bb[c], acc[r][c]);
    }

    #pragma unroll
    for (int r = 0; r < 4; r++) {
        float xv2 = x2s[ty * 4 + r];
        #pragma unroll
        for (int c = 0; c < 4; c++)
            ts[ty * 4 + r][tx * 4 + c] = fmaf(-2.f, acc[r][c], xv2 + y2s[tx * 4 + c]);
    }
    __syncthreads();

    for (int idx = tid; idx < 64 * 64; idx += 256) {
        int ii = idx >> 6;
        int jj = idx & 63;
        int r  = i0 + ii;
        g_D[((size_t)(b * 512 + r)) * RW + (size_t)(j0 + jj + (r & 31))]
            = ts[ii][jj] * F_L2E;
    }
}

// ---------------------------------------------------------------------------
// Kernel 2: soft-DTW wavefront, 4 columns/iteration, lane-skew 1.
// 64 blocks x 512 threads = 16 warps; thread t owns row i = t+1 (1-based).
// Warp-local iteration n: lane l computes cols j = 4n-l+1 .. 4n-l+4 via
// c1 -> shfl -> c2 -> shfl -> c3 -> shfl -> c4. Chunks of 4 iterations.
// Path: 34 own chunks + 15 hops x 2-chunk lag = 64 chunk-times (~256 iters).
// Boundary ring[w+1][pos], pos = col+30: producer lane31 STS.128 at pos 4n;
// consumer lane0 uses one LDS.128 at pos 4n+32 (+2 carried regs).
// Values carry an implicit log2(e) factor (D pre-scaled).
// ---------------------------------------------------------------------------
__global__ __launch_bounds__(512) void dtw_kernel(float* __restrict__ out)
{
    __shared__ __align__(16) float ring[17][576];
    __shared__ int prog[17];

    const int b    = blockIdx.x;
    const int tid  = threadIdx.x;
    const int lane = tid & 31;
    const int w    = tid >> 5;
    const bool lane0 = (lane == 0);

    for (int idx = tid; idx < 17 * 576; idx += 512) ((float*)ring)[idx] = BIGV;
    if (tid < 17) prog[tid] = 0;
    __syncthreads();
    if (tid == 0) ring[0][30] = 0.0f;        // R[0][0] = 0 (pos = col 0 + 30)
    __syncthreads();

    const float* __restrict__ Dp    = g_D + ((size_t)(b * 512) + tid) * RW;
    const float* __restrict__ ringR = ring[w];
    float*       __restrict__ ringW = ring[w + 1];

    float v4p = BIGV, sc3 = BIGV, sc4 = BIGV;   // left / neighbor-c3 / neighbor-c4 carries
    float rgA, rgB;                              // ring carries: cols 4n, 4n+1
    int pcache = 0;

    float4 cur[4], nxt[4];
    #pragma unroll
    for (int s = 0; s < 4; ++s) cur[s] = *(const float4*)(Dp + 4 * s);

#define DTW_WAIT(CH) do {                                                       \
        if (w) {                                                                \
            int need_ = 16 * (CH) + 17; if (need_ > 512) need_ = 512;           \
            if (pcache < need_) {                                               \
                int p_ = ld_acquire_shared(&prog[w]);                           \
                while (p_ < need_) { __nanosleep(32);                           \
                                     p_ = ld_acquire_shared(&prog[w]); }        \
                pcache = p_;                                                    \
            }                                                                   \
        }                                                                       \
    } while (0)

#define DTW_PUB(CH) do {                                                        \
        int pub_ = 16 * (CH) - 15; if (pub_ > 512) pub_ = 512;                  \
        if (lane == 31 && pub_ > 0) st_release_shared(&prog[w + 1], pub_);      \
    } while (0)

// PHASE: 0 = ramp-in (cols may be < 1), 1 = steady, 2 = ramp-out (cols may be > 512)
#define DTW_ITER(S, NV, PHASE, LAST) do {                                       \
        float4 dv = cur[S];                                                     \
        float4 rq = *(const float4*)&ringR[4 * (NV) + 32];                      \
        int jb_ = 4 * (NV) - lane;                                              \
        float up1 = lane0 ? rgB : sc4;                                          \
        float dg1 = lane0 ? rgA : sc3;                                          \
        float v1 = smin3(dg1, up1, v4p) + dv.x;                                 \
        if (PHASE == 0) v1 = (jb_ + 1 >= 1)   ? v1 : BIGV;                      \
        if (PHASE == 2) v1 = (jb_ + 1 <= 512) ? v1 : BIGV;                      \
        float s1 = __shfl_up_sync(0xffffffffu, v1, 1);                          \
        float up2 = lane0 ? rq.x : s1;                                          \
        float v2 = smin3(up1, up2, v1) + dv.y;                                  \
        if (PHASE == 0) v2 = (jb_ + 2 >= 1)   ? v2 : BIGV;                      \
        if (PHASE == 2) v2 = (jb_ + 2 <= 512) ? v2 : BIGV;                      \
        float s2 = __shfl_up_sync(0xffffffffu, v2, 1);                          \
        float up3 = lane0 ? rq.y : s2;                                          \
        float v3 = smin3(up2, up3, v2) + dv.z;                                  \
        if (PHASE == 0) v3 = (jb_ + 3 >= 1)   ? v3 : BIGV;                      \
        if (PHASE == 2) v3 = (jb_ + 3 <= 512) ? v3 : BIGV;                      \
        if (LAST) { if (tid == 511) out[b] = v3 * F_LN2; }                      \
        float s3 = __shfl_up_sync(0xffffffffu, v3, 1);                          \
        float up4 = lane0 ? rq.z : s3;                                          \
        float v4 = smin3(up3, up4, v3) + dv.w;                                  \
        if (PHASE == 0) v4 = (jb_ + 4 >= 1)   ? v4 : BIGV;                      \
        if (PHASE == 2) v4 = (jb_ + 4 <= 512) ? v4 : BIGV;                      \
        float s4 = __shfl_up_sync(0xffffffffu, v4, 1);                          \
        sc3 = s3; sc4 = s4; v4p = v4; rgA = rq.z; rgB = rq.w;                   \
        if (PHASE == 0) {                                                       \
            if (lane == 31) {                                                   \
                int base_ = 4 * (NV);                                           \
                if (jb_ + 1 >= 1) ringW[base_ + 0] = v1;                        \
                if (jb_ + 2 >= 1) ringW[base_ + 1] = v2;                        \
                if (jb_ + 3 >= 1) ringW[base_ + 2] = v3;                        \
                if (jb_ + 4 >= 1) ringW[base_ + 3] = v4;                        \
            }                                                                   \
        } else {                                                                \
            if (lane == 31)                                                     \
                *(float4*)&ringW[4 * (NV)] = make_float4(v1, v2, v3, v4);       \
        }                                                                       \
    } while (0)

    // Initial wait (chunk 0 needs ring cols through 17), then load ring carries.
    DTW_WAIT(0);
    rgA = ringR[30];    // col 0: 0.0 for w==0, BIG otherwise (or producer value)
    rgB = ringR[31];    // col 1

    // ---- ramp-in: chunks 0..1 (n = 0..7) ----
    #pragma unroll
    for (int ch = 0; ch < 2; ++ch) {
        if (ch) DTW_WAIT(ch);
        #pragma unroll
        for (int s = 0; s < 4; ++s)
            nxt[s] = *(const float4*)(Dp + 16 * (ch + 1) + 4 * s);
        DTW_ITER(0, 4 * ch + 0, 0, false);
        DTW_ITER(1, 4 * ch + 1, 0, false);
        DTW_ITER(2, 4 * ch + 2, 0, false);
        DTW_ITER(3, 4 * ch + 3, 0, false);
        #pragma unroll
        for (int s = 0; s < 4; ++s) cur[s] = nxt[s];
        DTW_PUB(ch);
    }

    // ---- steady: chunks 2..31 (n = 8..127), all cells valid ----
    #pragma unroll 1
    for (int ch = 2; ch < 32; ++ch) {
        DTW_WAIT(ch);
        #pragma unroll
        for (int s = 0; s < 4; ++s)
            nxt[s] = *(const float4*)(Dp + 16 * (ch + 1) + 4 * s);
        DTW_ITER(0, 4 * ch + 0, 1, false);
        DTW_ITER(1, 4 * ch + 1, 1, false);
        DTW_ITER(2, 4 * ch + 2, 1, false);
        DTW_ITER(3, 4 * ch + 3, 1, false);
        #pragma unroll
        for (int s = 0; s < 4; ++s) cur[s] = nxt[s];
        DTW_PUB(ch);
    }

    // ---- ramp-out: chunks 32..33 (n = 128..135) ----
    {
        DTW_WAIT(32);
        #pragma unroll
        for (int s = 0; s < 4; ++s)
            nxt[s] = *(const float4*)(Dp + 16 * 33 + 4 * s);
        DTW_ITER(0, 128, 2, false);
        DTW_ITER(1, 129, 2, false);
        DTW_ITER(2, 130, 2, false);
        DTW_ITER(3, 131, 2, false);
        #pragma unroll
        for (int s = 0; s < 4; ++s) cur[s] = nxt[s];
        DTW_PUB(32);

        DTW_WAIT(33);
        DTW_ITER(0, 132, 2, false);
        DTW_ITER(1, 133, 2, false);
        DTW_ITER(2, 134, 2, false);
        DTW_ITER(3, 135, 2, true);     // v3 at n=135: col 512 of row 512 -> out
        DTW_PUB(33);
    }

#undef DTW_ITER
#undef DTW_PUB
#undef DTW_WAIT
}

extern "C" void kernel_launch(void* const* d_in, const int* in_sizes, int n_in,
                              void* d_out, int out_size)
{
    const float* x = (const float*)d_in[0];
    const float* y = (const float*)d_in[1];
    float* out = (float*)d_out;

    dim3 g1(8, 8, 64);
    sqdist_kernel<<<g1, 256>>>(x, y);
    dtw_kernel<<<64, 512>>>(out);
}